// round 12
// baseline (speedup 1.0000x reference)
#include <cuda_runtime.h>
#include <cuda_fp16.h>
#include <cstdint>

#define NQ 8
#define NL 4

// U fp16, K-major: rows 0..255 Re, 256..511 Im; 256 K-cols each. Row stride 512B.
__device__ __align__(16) __half g_U[512 * 256];
__device__ int g_ctr;

// ---------------------------------------------------------------- K1: build U
__global__ void build_u_kernel(const float* __restrict__ w) {
    int gw = (blockIdx.x * blockDim.x + threadIdx.x) >> 5;
    int lane = threadIdx.x & 31;
    if (gw >= 256) return;
    int j = gw;
    float re[8], im[8];
#pragma unroll
    for (int i = 0; i < 8; i++) { re[i] = 0.f; im[i] = 0.f; }
    if (lane == (j >> 3)) re[j & 7] = 1.0f;

    for (int l = 0; l < NL; l++) {
#pragma unroll
        for (int q = 0; q < NQ; q++) {
            float th = w[(l * NQ + q) * 2 + 0];
            float tz = w[(l * NQ + q) * 2 + 1];
            float c, s, pr, pi2;
            __sincosf(0.5f * th, &s, &c);
            __sincosf(0.5f * tz, &pi2, &pr);
            int bp = 7 - q;
            if (bp >= 3) {
                int lb = bp - 3;
                int myb = (lane >> lb) & 1;
                float oc = myb ? s : -s;
                float ph = myb ? pi2 : -pi2;
#pragma unroll
                for (int i = 0; i < 8; i++) {
                    float ore = __shfl_xor_sync(0xffffffffu, re[i], 1 << lb);
                    float oim = __shfl_xor_sync(0xffffffffu, im[i], 1 << lb);
                    float ur = c * re[i] + oc * ore;
                    float ui = c * im[i] + oc * oim;
                    re[i] = pr * ur - ph * ui;
                    im[i] = pr * ui + ph * ur;
                }
            } else {
                int mm = 1 << bp;
#pragma unroll
                for (int i = 0; i < 8; i++) {
                    if (i & mm) continue;
                    int i1 = i | mm;
                    float ur0 = c * re[i] - s * re[i1], ui0 = c * im[i] - s * im[i1];
                    float ur1 = s * re[i] + c * re[i1], ui1 = s * im[i] + c * im[i1];
                    re[i]  = pr * ur0 + pi2 * ui0;  im[i]  = pr * ui0 - pi2 * ur0;
                    re[i1] = pr * ur1 - pi2 * ui1;  im[i1] = pr * ui1 + pi2 * ur1;
                }
            }
        }
#pragma unroll
        for (int cc = 0; cc < 7; cc++) {
            int cb = 7 - cc, tb = 6 - cc;
            if (tb >= 3) {
                int tm = 1 << (tb - 3);
                int ctrl = (lane >> (cb - 3)) & 1;
#pragma unroll
                for (int i = 0; i < 8; i++) {
                    float ore = __shfl_xor_sync(0xffffffffu, re[i], tm);
                    float oim = __shfl_xor_sync(0xffffffffu, im[i], tm);
                    if (ctrl) { re[i] = ore; im[i] = oim; }
                }
            } else if (cb == 3) {
                if (lane & 1) {
#pragma unroll
                    for (int i = 0; i < 4; i++) {
                        float tr = re[i]; re[i] = re[i + 4]; re[i + 4] = tr;
                        float ti = im[i]; im[i] = im[i + 4]; im[i + 4] = ti;
                    }
                }
            } else {
                int tmsk = 1 << tb;
#pragma unroll
                for (int i = 0; i < 8; i++) {
                    if (((i >> cb) & 1) && !((i >> tb) & 1)) {
                        int i1 = i | tmsk;
                        float tr = re[i]; re[i] = re[i1]; re[i1] = tr;
                        float ti = im[i]; im[i] = im[i1]; im[i1] = ti;
                    }
                }
            }
        }
    }
#pragma unroll
    for (int i = 0; i < 8; i++) {
        int k = lane * 8 + i;
        g_U[k * 256 + j] = __float2half(re[i]);
        g_U[(k + 256) * 256 + j] = __float2half(im[i]);
    }
}

// ---------------------------------------------------------------- helpers
__device__ __forceinline__ uint32_t s2u(const void* p) {
    uint32_t r;
    asm("{ .reg .u64 t; cvta.to.shared.u64 t, %1; cvt.u32.u64 %0, t; }" : "=r"(r) : "l"(p));
    return r;
}

__device__ __forceinline__ void ldsm4(uint32_t& r0, uint32_t& r1, uint32_t& r2, uint32_t& r3,
                                      uint32_t addr) {
    asm volatile("ldmatrix.sync.aligned.m8n8.x4.shared.b16 {%0,%1,%2,%3}, [%4];"
                 : "=r"(r0), "=r"(r1), "=r"(r2), "=r"(r3) : "r"(addr));
}

__device__ __forceinline__ void mma16816(float* c, const uint32_t* a, uint32_t b0, uint32_t b1) {
    asm volatile(
        "mma.sync.aligned.m16n8k16.row.col.f32.f16.f16.f32 "
        "{%0,%1,%2,%3}, {%4,%5,%6,%7}, {%8,%9}, {%0,%1,%2,%3};"
        : "+f"(c[0]), "+f"(c[1]), "+f"(c[2]), "+f"(c[3])
        : "r"(a[0]), "r"(a[1]), "r"(a[2]), "r"(a[3]), "r"(b0), "r"(b1));
}

// B chunk prefetch: 64 rows (32 Re + 32 Im) x 512B, XOR-swizzled, via cp.async.
// cc = global chunk index 0..7. 128 threads -> 16 x 16B each.
#define PREFETCH(cc, bufi)                                                          \
    {                                                                               \
        _Pragma("unroll") for (int i_ = 0; i_ < 16; i_++) {                         \
            int idx_ = t + i_ * 128;                                                \
            int row_ = idx_ >> 5, kg_ = idx_ & 31;                                  \
            int g_ = 32 * (cc) + (row_ & 31) + ((row_ & 32) << 3);                  \
            const __half* src_ = g_U + g_ * 256 + kg_ * 8;                          \
            uint32_t dst_ = sb + (bufi) * 32768 + row_ * 512 +                      \
                            ((kg_ * 16) ^ ((row_ & 7) << 4));                       \
            asm volatile("cp.async.cg.shared.global [%0], [%1], 16;"                \
                         :: "r"(dst_), "l"(src_));                                  \
        }                                                                           \
        asm volatile("cp.async.commit_group;" ::: "memory");                        \
    }

// ---------------------------------------------------------------- K2
// Persistent: grid 296 (2 CTAs/SM everywhere), block 128 (4 warps, M=32/warp).
// Work unit = (tile of 128 rows) x (2 of 8 N-chunks): 2048 units via atomic ctr.
// Partial marginals merged into out with atomicAdd (out zeroed by launch).
__global__ void __launch_bounds__(128, 2) qsim_kernel(const float* __restrict__ x,
                                                      float* __restrict__ out) {
    extern __shared__ char smem[];
    __shared__ int s_u;
    uint32_t sb = s2u(smem);
    int t = threadIdx.x, w = t >> 5, l = t & 31, m = l & 3;

    // ---- ldmatrix per-lane addressing (unit-invariant)
    int mR = l >> 3;
    int Rre = ((mR >> 1) << 3) + (l & 7);
    uint32_t offRe = Rre * 512;
    uint32_t koff = (mR & 1) << 4;
    uint32_t xr = (Rre & 7) << 4;
    float s6 = 1.f - 2.f * (float)(m & 1);
    float s5 = 1.f - 2.f * (float)(m >> 1);

    while (true) {
        if (t == 0) s_u = atomicAdd(&g_ctr, 1);
        __syncthreads();          // broadcast s_u + guard buffer reuse
        int u = s_u;
        if (u >= 2048) break;
        int tile = u >> 2, qr = u & 3;      // chunks qr*2, qr*2+1

        PREFETCH(qr * 2, 0);
        PREFETCH(qr * 2 + 1, 1);

        // ---- A fragments: 4 rows/thread (rg x rr), overlaps the cp.async flight
        uint32_t A[2][16][4];
#pragma unroll
        for (int rg = 0; rg < 2; rg++) {
#pragma unroll
            for (int rr = 0; rr < 2; rr++) {
                int row = tile * 128 + w * 32 + rg * 16 + rr * 8 + (l >> 2);
                const float4* xr4 = (const float4*)(x + (size_t)row * 8);
                float4 x0 = xr4[0], x1 = xr4[1];
                float xq[8] = {x0.x, x0.y, x0.z, x0.w, x1.x, x1.y, x1.z, x1.w};
                float c[8], s[8];
#pragma unroll
                for (int q = 0; q < 8; q++) __sincosf(0.5f * xq[q], &s[q], &c[q]);
                float hh[16];
                hh[0] = 1.f;
                int n = 1;
#pragma unroll
                for (int q = 0; q < 4; q++) {
#pragma unroll
                    for (int mm = 15; mm >= 0; mm--) if (mm < n) {
                        float v = hh[mm];
                        hh[2 * mm] = v * c[q];
                        hh[2 * mm + 1] = v * s[q];
                    }
                    n *= 2;
                }
                float pa = ((m >> 1) ? s[5] : c[5]) * ((m & 1) ? s[6] : c[6]);
                float loA = c[4] * pa * c[7], loB = c[4] * pa * s[7];
                float loC = s[4] * pa * c[7], loD = s[4] * pa * s[7];
#pragma unroll
                for (int ss = 0; ss < 16; ss++) {
                    float h = hh[ss];
                    __half2 plo = __floats2half2_rn(h * loA, h * loB);
                    __half2 phi = __floats2half2_rn(h * loC, h * loD);
                    A[rg][ss][rr] = *(uint32_t*)&plo;
                    A[rg][ss][2 + rr] = *(uint32_t*)&phi;
                }
            }
        }

        // ---- accumulators per rowset rs = rg*2+rr
        float o7[4] = {0, 0, 0, 0}, o4a[4] = {0, 0, 0, 0}, tot[4] = {0, 0, 0, 0};
        float a3[4] = {0, 0, 0, 0}, a2[4] = {0, 0, 0, 0};
        float a1[4] = {0, 0, 0, 0}, a0q[4] = {0, 0, 0, 0};

#pragma unroll
        for (int c = 0; c < 2; c++) {
            if (c == 0) asm volatile("cp.async.wait_group 1;" ::: "memory");
            else        asm volatile("cp.async.wait_group 0;" ::: "memory");
            __syncthreads();
            uint32_t bb = sb + c * 32768;

#pragma unroll
            for (int ng = 0; ng < 2; ng++) {
                uint32_t bRe = bb + ng * 8192 + offRe;
                uint32_t bIm = bRe + 16384;

                float cR0[2][4] = {}, cR1[2][4] = {}, cI0[2][4] = {}, cI1[2][4] = {};
#pragma unroll
                for (int ss = 0; ss < 16; ss++) {
                    uint32_t kb = (((uint32_t)(ss * 32)) | koff) ^ xr;
                    uint32_t br0, br1, br2, br3, bi0, bi1, bi2, bi3;
                    ldsm4(br0, br1, br2, br3, bRe + kb);
                    ldsm4(bi0, bi1, bi2, bi3, bIm + kb);
#pragma unroll
                    for (int rg = 0; rg < 2; rg++) {
                        mma16816(cR0[rg], A[rg][ss], br0, br1);
                        mma16816(cR1[rg], A[rg][ss], br2, br3);
                        mma16816(cI0[rg], A[rg][ss], bi0, bi1);
                        mma16816(cI1[rg], A[rg][ss], bi2, bi3);
                    }
                }
                int cN = (qr * 2 + c) * 2 + ng;
                float sc3 = 1.f - 2.f * (float)(cN & 1);
                float sc2 = 1.f - 2.f * (float)((cN >> 1) & 1);
                float sc1 = 1.f - 2.f * (float)((cN >> 2) & 1);
                float sc0 = 1.f - 2.f * (float)((cN >> 3) & 1);
#pragma unroll
                for (int rg = 0; rg < 2; rg++) {
#pragma unroll
                    for (int rr = 0; rr < 2; rr++) {
                        int rs = rg * 2 + rr;
                        int i0 = rr * 2, i1 = rr * 2 + 1;
                        float p00 = fmaf(cR0[rg][i0], cR0[rg][i0], cI0[rg][i0] * cI0[rg][i0]);
                        float p01 = fmaf(cR0[rg][i1], cR0[rg][i1], cI0[rg][i1] * cI0[rg][i1]);
                        float p10 = fmaf(cR1[rg][i0], cR1[rg][i0], cI1[rg][i0] * cI1[rg][i0]);
                        float p11 = fmaf(cR1[rg][i1], cR1[rg][i1], cI1[rg][i1] * cI1[rg][i1]);
                        float s0 = p00 + p01, d0 = p00 - p01;
                        float s1 = p10 + p11, d1 = p10 - p11;
                        o7[rs] += d0 + d1;
                        o4a[rs] += s0 - s1;
                        float tc = s0 + s1;
                        tot[rs] += tc;
                        a3[rs] = fmaf(sc3, tc, a3[rs]);
                        a2[rs] = fmaf(sc2, tc, a2[rs]);
                        a1[rs] = fmaf(sc1, tc, a1[rs]);
                        a0q[rs] = fmaf(sc0, tc, a0q[rs]);
                    }
                }
            }
        }

        // ---- merge partials: quad reduce, then RED.f32 into out
#pragma unroll
        for (int rs = 0; rs < 4; rs++) {
            float o[8];
            o[0] = a0q[rs]; o[1] = a1[rs]; o[2] = a2[rs]; o[3] = a3[rs];
            o[4] = o4a[rs]; o[5] = s5 * tot[rs]; o[6] = s6 * tot[rs]; o[7] = o7[rs];
#pragma unroll
            for (int k = 0; k < 8; k++) {
                o[k] += __shfl_xor_sync(0xffffffffu, o[k], 1);
                o[k] += __shfl_xor_sync(0xffffffffu, o[k], 2);
            }
            if (m == 0) {
                int row = tile * 128 + w * 32 + (rs >> 1) * 16 + (rs & 1) * 8 + (l >> 2);
                float* op = out + (size_t)row * 8;
#pragma unroll
                for (int k = 0; k < 8; k++) atomicAdd(op + k, o[k]);
            }
        }
    }
}

// ---------------------------------------------------------------- launch
extern "C" void kernel_launch(void* const* d_in, const int* in_sizes, int n_in,
                              void* d_out, int out_size) {
    const float* x = (const float*)d_in[0];
    const float* w = (const float*)d_in[1];
    float* out = (float*)d_out;
    void* ctr_addr = nullptr;
    cudaGetSymbolAddress(&ctr_addr, g_ctr);
    cudaMemsetAsync(ctr_addr, 0, sizeof(int));
    cudaMemsetAsync(out, 0, (size_t)out_size * sizeof(float));
    cudaFuncSetAttribute(qsim_kernel, cudaFuncAttributeMaxDynamicSharedMemorySize, 65536);
    build_u_kernel<<<64, 128>>>(w);
    qsim_kernel<<<296, 128, 65536>>>(x, out);
}

// round 14
// speedup vs baseline: 1.1847x; 1.1847x over previous
#include <cuda_runtime.h>
#include <cuda_fp16.h>
#include <cstdint>

#define NQ 8
#define NL 4

// U fp16, K-major: rows 0..255 Re, 256..511 Im; 256 K-cols each. Row stride 512B.
__device__ __align__(16) __half g_U[512 * 256];

// ---------------------------------------------------------------- K1: build U
__global__ void build_u_kernel(const float* __restrict__ w) {
    int gw = (blockIdx.x * blockDim.x + threadIdx.x) >> 5;
    int lane = threadIdx.x & 31;
    if (gw >= 256) return;
    int j = gw;
    float re[8], im[8];
#pragma unroll
    for (int i = 0; i < 8; i++) { re[i] = 0.f; im[i] = 0.f; }
    if (lane == (j >> 3)) re[j & 7] = 1.0f;

    for (int l = 0; l < NL; l++) {
#pragma unroll
        for (int q = 0; q < NQ; q++) {
            float th = w[(l * NQ + q) * 2 + 0];
            float tz = w[(l * NQ + q) * 2 + 1];
            float c, s, pr, pi2;
            __sincosf(0.5f * th, &s, &c);
            __sincosf(0.5f * tz, &pi2, &pr);
            int bp = 7 - q;
            if (bp >= 3) {
                int lb = bp - 3;
                int myb = (lane >> lb) & 1;
                float oc = myb ? s : -s;
                float ph = myb ? pi2 : -pi2;
#pragma unroll
                for (int i = 0; i < 8; i++) {
                    float ore = __shfl_xor_sync(0xffffffffu, re[i], 1 << lb);
                    float oim = __shfl_xor_sync(0xffffffffu, im[i], 1 << lb);
                    float ur = c * re[i] + oc * ore;
                    float ui = c * im[i] + oc * oim;
                    re[i] = pr * ur - ph * ui;
                    im[i] = pr * ui + ph * ur;
                }
            } else {
                int mm = 1 << bp;
#pragma unroll
                for (int i = 0; i < 8; i++) {
                    if (i & mm) continue;
                    int i1 = i | mm;
                    float ur0 = c * re[i] - s * re[i1], ui0 = c * im[i] - s * im[i1];
                    float ur1 = s * re[i] + c * re[i1], ui1 = s * im[i] + c * im[i1];
                    re[i]  = pr * ur0 + pi2 * ui0;  im[i]  = pr * ui0 - pi2 * ur0;
                    re[i1] = pr * ur1 - pi2 * ui1;  im[i1] = pr * ui1 + pi2 * ur1;
                }
            }
        }
#pragma unroll
        for (int cc = 0; cc < 7; cc++) {
            int cb = 7 - cc, tb = 6 - cc;
            if (tb >= 3) {
                int tm = 1 << (tb - 3);
                int ctrl = (lane >> (cb - 3)) & 1;
#pragma unroll
                for (int i = 0; i < 8; i++) {
                    float ore = __shfl_xor_sync(0xffffffffu, re[i], tm);
                    float oim = __shfl_xor_sync(0xffffffffu, im[i], tm);
                    if (ctrl) { re[i] = ore; im[i] = oim; }
                }
            } else if (cb == 3) {
                if (lane & 1) {
#pragma unroll
                    for (int i = 0; i < 4; i++) {
                        float tr = re[i]; re[i] = re[i + 4]; re[i + 4] = tr;
                        float ti = im[i]; im[i] = im[i + 4]; im[i + 4] = ti;
                    }
                }
            } else {
                int tmsk = 1 << tb;
#pragma unroll
                for (int i = 0; i < 8; i++) {
                    if (((i >> cb) & 1) && !((i >> tb) & 1)) {
                        int i1 = i | tmsk;
                        float tr = re[i]; re[i] = re[i1]; re[i1] = tr;
                        float ti = im[i]; im[i] = im[i1]; im[i1] = ti;
                    }
                }
            }
        }
    }
#pragma unroll
    for (int i = 0; i < 8; i++) {
        int k = lane * 8 + i;
        g_U[k * 256 + j] = __float2half(re[i]);
        g_U[(k + 256) * 256 + j] = __float2half(im[i]);
    }
}

// ---------------------------------------------------------------- helpers
__device__ __forceinline__ uint32_t s2u(const void* p) {
    uint32_t r;
    asm("{ .reg .u64 t; cvta.to.shared.u64 t, %1; cvt.u32.u64 %0, t; }" : "=r"(r) : "l"(p));
    return r;
}

__device__ __forceinline__ void ldsm4(uint32_t& r0, uint32_t& r1, uint32_t& r2, uint32_t& r3,
                                      uint32_t addr) {
    asm volatile("ldmatrix.sync.aligned.m8n8.x4.shared.b16 {%0,%1,%2,%3}, [%4];"
                 : "=r"(r0), "=r"(r1), "=r"(r2), "=r"(r3) : "r"(addr));
}

__device__ __forceinline__ void mma16816(float* c, uint32_t a0, uint32_t a1, uint32_t a2,
                                         uint32_t a3, uint32_t b0, uint32_t b1) {
    asm volatile(
        "mma.sync.aligned.m16n8k16.row.col.f32.f16.f16.f32 "
        "{%0,%1,%2,%3}, {%4,%5,%6,%7}, {%8,%9}, {%0,%1,%2,%3};"
        : "+f"(c[0]), "+f"(c[1]), "+f"(c[2]), "+f"(c[3])
        : "r"(a0), "r"(a1), "r"(a2), "r"(a3), "r"(b0), "r"(b1));
}

__device__ __forceinline__ uint32_t hm2(uint32_t a, uint32_t b) {
    uint32_t d;
    asm("mul.f16x2 %0, %1, %2;" : "=r"(d) : "r"(a), "r"(b));
    return d;
}

// B chunk prefetch: 64 rows (32 Re + 32 Im) x 512B, XOR-swizzled, via cp.async.
// 128 threads -> 16 x 16B each.
#define PREFETCH(cc, bufi)                                                          \
    {                                                                               \
        _Pragma("unroll") for (int i_ = 0; i_ < 16; i_++) {                         \
            int idx_ = t + i_ * 128;                                                \
            int row_ = idx_ >> 5, kg_ = idx_ & 31;                                  \
            int g_ = 32 * (cc) + (row_ & 31) + ((row_ & 32) << 3);                  \
            const __half* src_ = g_U + g_ * 256 + kg_ * 8;                          \
            uint32_t dst_ = sb + (bufi) * 32768 + row_ * 512 +                      \
                            ((kg_ * 16) ^ ((row_ & 7) << 4));                       \
            asm volatile("cp.async.cg.shared.global [%0], [%1], 16;"                \
                         :: "r"(dst_), "l"(src_));                                  \
        }                                                                           \
        asm volatile("cp.async.commit_group;" ::: "memory");                        \
    }

// ---------------------------------------------------------------- K2
// M=32 rows/warp, 4 warps/CTA, grid 512. 8 chunks of 32 N-rows, 3-stage (96KB).
// A stored as plo halves only (64 regs); phi = plo * tan(x4/2) via mul.f16x2.
__global__ void __launch_bounds__(128, 2) qsim_kernel(const float* __restrict__ x,
                                                      float* __restrict__ out) {
    extern __shared__ char smem[];
    uint32_t sb = s2u(smem);
    int t = threadIdx.x, w = t >> 5, l = t & 31, m = l & 3;
    int tile = blockIdx.x;

    PREFETCH(0, 0);
    PREFETCH(1, 1);

    // ---- A factors: plo[rg][ss][rr] + per-row tan4 (phi synthesized in loop)
    uint32_t plo[2][16][2], t4h[2][2];
#pragma unroll
    for (int rg = 0; rg < 2; rg++) {
#pragma unroll
        for (int rr = 0; rr < 2; rr++) {
            int row = tile * 128 + w * 32 + rg * 16 + rr * 8 + (l >> 2);
            const float4* xr4 = (const float4*)(x + (size_t)row * 8);
            float4 x0 = xr4[0], x1 = xr4[1];
            float xq[8] = {x0.x, x0.y, x0.z, x0.w, x1.x, x1.y, x1.z, x1.w};
            float c[8], s[8];
#pragma unroll
            for (int q = 0; q < 8; q++) __sincosf(0.5f * xq[q], &s[q], &c[q]);
            float hh[16];
            hh[0] = 1.f;
            int n = 1;
#pragma unroll
            for (int q = 0; q < 4; q++) {
#pragma unroll
                for (int mm = 15; mm >= 0; mm--) if (mm < n) {
                    float v = hh[mm];
                    hh[2 * mm] = v * c[q];
                    hh[2 * mm + 1] = v * s[q];
                }
                n *= 2;
            }
            float pa = ((m >> 1) ? s[5] : c[5]) * ((m & 1) ? s[6] : c[6]);
            float loA = c[4] * pa * c[7], loB = c[4] * pa * s[7];
            __half2 tt = __half2half2(__float2half_rn(__fdividef(s[4], c[4])));
            t4h[rg][rr] = *(uint32_t*)&tt;
#pragma unroll
            for (int ss = 0; ss < 16; ss++) {
                float h = hh[ss];
                __half2 p = __floats2half2_rn(h * loA, h * loB);
                plo[rg][ss][rr] = *(uint32_t*)&p;
            }
        }
    }

    // ---- ldmatrix per-lane addressing
    int mR = l >> 3;
    int Rre = ((mR >> 1) << 3) + (l & 7);
    uint32_t offRe = Rre * 512;
    uint32_t koff = (mR & 1) << 4;
    uint32_t xr = (Rre & 7) << 4;

    // ---- accumulators per rowset rs = rg*2+rr
    float o7[4] = {0, 0, 0, 0}, o4a[4] = {0, 0, 0, 0}, tot[4] = {0, 0, 0, 0};
    float a3[4] = {0, 0, 0, 0}, a2[4] = {0, 0, 0, 0};
    float a1[4] = {0, 0, 0, 0}, a0q[4] = {0, 0, 0, 0};

    int cb = 0, pb = 2;
    for (int c = 0; c < 8; c++) {
        if (c < 7) asm volatile("cp.async.wait_group 1;" ::: "memory");
        else       asm volatile("cp.async.wait_group 0;" ::: "memory");
        __syncthreads();
        if (c + 2 < 8) {
            PREFETCH(c + 2, pb);
            pb = (pb == 2) ? 0 : pb + 1;
        }
        uint32_t bb = sb + cb * 32768;
        cb = (cb == 2) ? 0 : cb + 1;

#pragma unroll
        for (int ng = 0; ng < 2; ng++) {
            uint32_t bRe = bb + ng * 8192 + offRe;
            uint32_t bIm = bRe + 16384;

            float cR0[2][4] = {}, cR1[2][4] = {}, cI0[2][4] = {}, cI1[2][4] = {};
#pragma unroll
            for (int ss = 0; ss < 16; ss++) {
                uint32_t kb = (((uint32_t)(ss * 32)) | koff) ^ xr;
                uint32_t br0, br1, br2, br3, bi0, bi1, bi2, bi3;
                ldsm4(br0, br1, br2, br3, bRe + kb);
                ldsm4(bi0, bi1, bi2, bi3, bIm + kb);
#pragma unroll
                for (int rg = 0; rg < 2; rg++) {
                    uint32_t p0 = plo[rg][ss][0], p1 = plo[rg][ss][1];
                    uint32_t f0 = hm2(p0, t4h[rg][0]);
                    uint32_t f1 = hm2(p1, t4h[rg][1]);
                    mma16816(cR0[rg], p0, p1, f0, f1, br0, br1);
                    mma16816(cR1[rg], p0, p1, f0, f1, br2, br3);
                    mma16816(cI0[rg], p0, p1, f0, f1, bi0, bi1);
                    mma16816(cI1[rg], p0, p1, f0, f1, bi2, bi3);
                }
            }
            int cN = c * 2 + ng;
            float sc3 = 1.f - 2.f * (float)(cN & 1);
            float sc2 = 1.f - 2.f * (float)((cN >> 1) & 1);
            float sc1 = 1.f - 2.f * (float)((cN >> 2) & 1);
            float sc0 = 1.f - 2.f * (float)((cN >> 3) & 1);
#pragma unroll
            for (int rg = 0; rg < 2; rg++) {
#pragma unroll
                for (int rr = 0; rr < 2; rr++) {
                    int rs = rg * 2 + rr;
                    int i0 = rr * 2, i1 = rr * 2 + 1;
                    float p00 = fmaf(cR0[rg][i0], cR0[rg][i0], cI0[rg][i0] * cI0[rg][i0]);
                    float p01 = fmaf(cR0[rg][i1], cR0[rg][i1], cI0[rg][i1] * cI0[rg][i1]);
                    float p10 = fmaf(cR1[rg][i0], cR1[rg][i0], cI1[rg][i0] * cI1[rg][i0]);
                    float p11 = fmaf(cR1[rg][i1], cR1[rg][i1], cI1[rg][i1] * cI1[rg][i1]);
                    float s0 = p00 + p01, d0 = p00 - p01;
                    float s1 = p10 + p11, d1 = p10 - p11;
                    o7[rs] += d0 + d1;
                    o4a[rs] += s0 - s1;
                    float tc = s0 + s1;
                    tot[rs] += tc;
                    a3[rs] = fmaf(sc3, tc, a3[rs]);
                    a2[rs] = fmaf(sc2, tc, a2[rs]);
                    a1[rs] = fmaf(sc1, tc, a1[rs]);
                    a0q[rs] = fmaf(sc0, tc, a0q[rs]);
                }
            }
        }
    }

    // ---- finish: per-thread fixed signs (n bits 1,2 <-> qubits 6,5), quad reduce
    float s6 = 1.f - 2.f * (float)(m & 1);
    float s5 = 1.f - 2.f * (float)(m >> 1);
#pragma unroll
    for (int rs = 0; rs < 4; rs++) {
        float o[8];
        o[0] = a0q[rs]; o[1] = a1[rs]; o[2] = a2[rs]; o[3] = a3[rs];
        o[4] = o4a[rs]; o[5] = s5 * tot[rs]; o[6] = s6 * tot[rs]; o[7] = o7[rs];
#pragma unroll
        for (int k = 0; k < 8; k++) {
            o[k] += __shfl_xor_sync(0xffffffffu, o[k], 1);
            o[k] += __shfl_xor_sync(0xffffffffu, o[k], 2);
        }
        if (m == 0) {
            int row = tile * 128 + w * 32 + (rs >> 1) * 16 + (rs & 1) * 8 + (l >> 2);
            float4* op = (float4*)(out + (size_t)row * 8);
            op[0] = make_float4(o[0], o[1], o[2], o[3]);
            op[1] = make_float4(o[4], o[5], o[6], o[7]);
        }
    }
}

// ---------------------------------------------------------------- launch
extern "C" void kernel_launch(void* const* d_in, const int* in_sizes, int n_in,
                              void* d_out, int out_size) {
    const float* x = (const float*)d_in[0];
    const float* w = (const float*)d_in[1];
    float* out = (float*)d_out;
    cudaFuncSetAttribute(qsim_kernel, cudaFuncAttributeMaxDynamicSharedMemorySize, 98304);
    build_u_kernel<<<64, 128>>>(w);
    qsim_kernel<<<512, 128, 98304>>>(x, out);
}

// round 15
// speedup vs baseline: 1.1994x; 1.0124x over previous
#include <cuda_runtime.h>
#include <cuda_fp16.h>
#include <cstdint>

#define NQ 8
#define NL 4

// U fp16, K-major: rows 0..255 Re, 256..511 Im; 256 K-cols each. Row stride 512B.
__device__ __align__(16) __half g_U[512 * 256];
__device__ int g_done;   // builder-CTA completion counter (memset 0 per launch)

// ---------------------------------------------------------------- helpers
__device__ __forceinline__ uint32_t s2u(const void* p) {
    uint32_t r;
    asm("{ .reg .u64 t; cvta.to.shared.u64 t, %1; cvt.u32.u64 %0, t; }" : "=r"(r) : "l"(p));
    return r;
}

__device__ __forceinline__ void ldsm4(uint32_t& r0, uint32_t& r1, uint32_t& r2, uint32_t& r3,
                                      uint32_t addr) {
    asm volatile("ldmatrix.sync.aligned.m8n8.x4.shared.b16 {%0,%1,%2,%3}, [%4];"
                 : "=r"(r0), "=r"(r1), "=r"(r2), "=r"(r3) : "r"(addr));
}

__device__ __forceinline__ void mma16816(float* c, const uint32_t* a, uint32_t b0, uint32_t b1) {
    asm volatile(
        "mma.sync.aligned.m16n8k16.row.col.f32.f16.f16.f32 "
        "{%0,%1,%2,%3}, {%4,%5,%6,%7}, {%8,%9}, {%0,%1,%2,%3};"
        : "+f"(c[0]), "+f"(c[1]), "+f"(c[2]), "+f"(c[3])
        : "r"(a[0]), "r"(a[1]), "r"(a[2]), "r"(a[3]), "r"(b0), "r"(b1));
}

// ---------------------------------------------------------------- U builder body
// One warp builds one column j of U (circuit simulation on basis state j).
__device__ void build_u_col(const float* __restrict__ w, int j, int lane) {
    float re[8], im[8];
#pragma unroll
    for (int i = 0; i < 8; i++) { re[i] = 0.f; im[i] = 0.f; }
    if (lane == (j >> 3)) re[j & 7] = 1.0f;

    for (int l = 0; l < NL; l++) {
#pragma unroll
        for (int q = 0; q < NQ; q++) {
            float th = w[(l * NQ + q) * 2 + 0];
            float tz = w[(l * NQ + q) * 2 + 1];
            float c, s, pr, pi2;
            __sincosf(0.5f * th, &s, &c);
            __sincosf(0.5f * tz, &pi2, &pr);
            int bp = 7 - q;
            if (bp >= 3) {
                int lb = bp - 3;
                int myb = (lane >> lb) & 1;
                float oc = myb ? s : -s;
                float ph = myb ? pi2 : -pi2;
#pragma unroll
                for (int i = 0; i < 8; i++) {
                    float ore = __shfl_xor_sync(0xffffffffu, re[i], 1 << lb);
                    float oim = __shfl_xor_sync(0xffffffffu, im[i], 1 << lb);
                    float ur = c * re[i] + oc * ore;
                    float ui = c * im[i] + oc * oim;
                    re[i] = pr * ur - ph * ui;
                    im[i] = pr * ui + ph * ur;
                }
            } else {
                int mm = 1 << bp;
#pragma unroll
                for (int i = 0; i < 8; i++) {
                    if (i & mm) continue;
                    int i1 = i | mm;
                    float ur0 = c * re[i] - s * re[i1], ui0 = c * im[i] - s * im[i1];
                    float ur1 = s * re[i] + c * re[i1], ui1 = s * im[i] + c * im[i1];
                    re[i]  = pr * ur0 + pi2 * ui0;  im[i]  = pr * ui0 - pi2 * ur0;
                    re[i1] = pr * ur1 - pi2 * ui1;  im[i1] = pr * ui1 + pi2 * ur1;
                }
            }
        }
#pragma unroll
        for (int cc = 0; cc < 7; cc++) {
            int cb = 7 - cc, tb = 6 - cc;
            if (tb >= 3) {
                int tm = 1 << (tb - 3);
                int ctrl = (lane >> (cb - 3)) & 1;
#pragma unroll
                for (int i = 0; i < 8; i++) {
                    float ore = __shfl_xor_sync(0xffffffffu, re[i], tm);
                    float oim = __shfl_xor_sync(0xffffffffu, im[i], tm);
                    if (ctrl) { re[i] = ore; im[i] = oim; }
                }
            } else if (cb == 3) {
                if (lane & 1) {
#pragma unroll
                    for (int i = 0; i < 4; i++) {
                        float tr = re[i]; re[i] = re[i + 4]; re[i + 4] = tr;
                        float ti = im[i]; im[i] = im[i + 4]; im[i + 4] = ti;
                    }
                }
            } else {
                int tmsk = 1 << tb;
#pragma unroll
                for (int i = 0; i < 8; i++) {
                    if (((i >> cb) & 1) && !((i >> tb) & 1)) {
                        int i1 = i | tmsk;
                        float tr = re[i]; re[i] = re[i1]; re[i1] = tr;
                        float ti = im[i]; im[i] = im[i1]; im[i1] = ti;
                    }
                }
            }
        }
    }
#pragma unroll
    for (int i = 0; i < 8; i++) {
        int k = lane * 8 + i;
        g_U[k * 256 + j] = __float2half(re[i]);
        g_U[(k + 256) * 256 + j] = __float2half(im[i]);
    }
}

// B chunk prefetch: 64 rows (32 Re + 32 Im) x 512B, XOR-swizzled, via cp.async.
// 128 threads -> 16 x 16B each.
#define PREFETCH(cc, bufi)                                                          \
    {                                                                               \
        _Pragma("unroll") for (int i_ = 0; i_ < 16; i_++) {                         \
            int idx_ = t + i_ * 128;                                                \
            int row_ = idx_ >> 5, kg_ = idx_ & 31;                                  \
            int g_ = 32 * (cc) + (row_ & 31) + ((row_ & 32) << 3);                  \
            const __half* src_ = g_U + g_ * 256 + kg_ * 8;                          \
            uint32_t dst_ = sb + (bufi) * 32768 + row_ * 512 +                      \
                            ((kg_ * 16) ^ ((row_ & 7) << 4));                       \
            asm volatile("cp.async.cg.shared.global [%0], [%1], 16;"                \
                         :: "r"(dst_), "l"(src_));                                  \
        }                                                                           \
        asm volatile("cp.async.commit_group;" ::: "memory");                        \
    }

// ---------------------------------------------------------------- fused kernel
// CTAs 0..63 build U (4 cols/warp-CTA) while all CTAs build A; spin until done.
// Then R5 mainloop: M=32/warp, 4 warps, 8 chunks of 32 N-rows, 3-stage (96KB).
__global__ void __launch_bounds__(128, 2) qsim_kernel(const float* __restrict__ x,
                                                      const float* __restrict__ wts,
                                                      float* __restrict__ out) {
    extern __shared__ char smem[];
    uint32_t sb = s2u(smem);
    int t = threadIdx.x, w = t >> 5, l = t & 31, m = l & 3;
    int tile = blockIdx.x;

    // ---- builders: CTAs 0..63, one column per warp (256 warps total)
    if (blockIdx.x < 64) {
        build_u_col(wts, blockIdx.x * 4 + w, l);
        __syncthreads();
        if (t == 0) { __threadfence(); atomicAdd(&g_done, 1); }
    }

    // ---- A fragments: 4 rows/thread (rg x rr) — overlaps the U build
    uint32_t A[2][16][4];
#pragma unroll
    for (int rg = 0; rg < 2; rg++) {
#pragma unroll
        for (int rr = 0; rr < 2; rr++) {
            int row = tile * 128 + w * 32 + rg * 16 + rr * 8 + (l >> 2);
            const float4* xr4 = (const float4*)(x + (size_t)row * 8);
            float4 x0 = xr4[0], x1 = xr4[1];
            float xq[8] = {x0.x, x0.y, x0.z, x0.w, x1.x, x1.y, x1.z, x1.w};
            float c[8], s[8];
#pragma unroll
            for (int q = 0; q < 8; q++) __sincosf(0.5f * xq[q], &s[q], &c[q]);
            float hh[16];
            hh[0] = 1.f;
            int n = 1;
#pragma unroll
            for (int q = 0; q < 4; q++) {
#pragma unroll
                for (int mm = 15; mm >= 0; mm--) if (mm < n) {
                    float v = hh[mm];
                    hh[2 * mm] = v * c[q];
                    hh[2 * mm + 1] = v * s[q];
                }
                n *= 2;
            }
            float pa = ((m >> 1) ? s[5] : c[5]) * ((m & 1) ? s[6] : c[6]);
            float loA = c[4] * pa * c[7], loB = c[4] * pa * s[7];
            float loC = s[4] * pa * c[7], loD = s[4] * pa * s[7];
#pragma unroll
            for (int ss = 0; ss < 16; ss++) {
                float h = hh[ss];
                __half2 plo = __floats2half2_rn(h * loA, h * loB);
                __half2 phi = __floats2half2_rn(h * loC, h * loD);
                A[rg][ss][rr] = *(uint32_t*)&plo;
                A[rg][ss][2 + rr] = *(uint32_t*)&phi;
            }
        }
    }

    // ---- wait for U completion (acquire), then prefetch B
    if (t == 0) {
        int v;
        do {
            asm volatile("ld.acquire.gpu.global.s32 %0, [%1];" : "=r"(v) : "l"(&g_done));
            if (v < 64) __nanosleep(128);
        } while (v < 64);
    }
    __syncthreads();

    PREFETCH(0, 0);
    PREFETCH(1, 1);

    // ---- ldmatrix per-lane addressing
    int mR = l >> 3;
    int Rre = ((mR >> 1) << 3) + (l & 7);
    uint32_t offRe = Rre * 512;
    uint32_t koff = (mR & 1) << 4;
    uint32_t xr = (Rre & 7) << 4;

    // ---- accumulators per rowset rs = rg*2+rr
    float o7[4] = {0, 0, 0, 0}, o4a[4] = {0, 0, 0, 0}, tot[4] = {0, 0, 0, 0};
    float a3[4] = {0, 0, 0, 0}, a2[4] = {0, 0, 0, 0};
    float a1[4] = {0, 0, 0, 0}, a0q[4] = {0, 0, 0, 0};

    int cb = 0, pb = 2;
    for (int c = 0; c < 8; c++) {
        if (c < 7) asm volatile("cp.async.wait_group 1;" ::: "memory");
        else       asm volatile("cp.async.wait_group 0;" ::: "memory");
        __syncthreads();
        if (c + 2 < 8) {
            PREFETCH(c + 2, pb);
            pb = (pb == 2) ? 0 : pb + 1;
        }
        uint32_t bb = sb + cb * 32768;
        cb = (cb == 2) ? 0 : cb + 1;

#pragma unroll
        for (int ng = 0; ng < 2; ng++) {
            uint32_t bRe = bb + ng * 8192 + offRe;
            uint32_t bIm = bRe + 16384;

            float cR0[2][4] = {}, cR1[2][4] = {}, cI0[2][4] = {}, cI1[2][4] = {};
#pragma unroll
            for (int ss = 0; ss < 16; ss++) {
                uint32_t kb = (((uint32_t)(ss * 32)) | koff) ^ xr;
                uint32_t br0, br1, br2, br3, bi0, bi1, bi2, bi3;
                ldsm4(br0, br1, br2, br3, bRe + kb);
                ldsm4(bi0, bi1, bi2, bi3, bIm + kb);
#pragma unroll
                for (int rg = 0; rg < 2; rg++) {
                    mma16816(cR0[rg], A[rg][ss], br0, br1);
                    mma16816(cR1[rg], A[rg][ss], br2, br3);
                    mma16816(cI0[rg], A[rg][ss], bi0, bi1);
                    mma16816(cI1[rg], A[rg][ss], bi2, bi3);
                }
            }
            int cN = c * 2 + ng;
            float sc3 = 1.f - 2.f * (float)(cN & 1);
            float sc2 = 1.f - 2.f * (float)((cN >> 1) & 1);
            float sc1 = 1.f - 2.f * (float)((cN >> 2) & 1);
            float sc0 = 1.f - 2.f * (float)((cN >> 3) & 1);
#pragma unroll
            for (int rg = 0; rg < 2; rg++) {
#pragma unroll
                for (int rr = 0; rr < 2; rr++) {
                    int rs = rg * 2 + rr;
                    int i0 = rr * 2, i1 = rr * 2 + 1;
                    float p00 = fmaf(cR0[rg][i0], cR0[rg][i0], cI0[rg][i0] * cI0[rg][i0]);
                    float p01 = fmaf(cR0[rg][i1], cR0[rg][i1], cI0[rg][i1] * cI0[rg][i1]);
                    float p10 = fmaf(cR1[rg][i0], cR1[rg][i0], cI1[rg][i0] * cI1[rg][i0]);
                    float p11 = fmaf(cR1[rg][i1], cR1[rg][i1], cI1[rg][i1] * cI1[rg][i1]);
                    float s0 = p00 + p01, d0 = p00 - p01;
                    float s1 = p10 + p11, d1 = p10 - p11;
                    o7[rs] += d0 + d1;
                    o4a[rs] += s0 - s1;
                    float tc = s0 + s1;
                    tot[rs] += tc;
                    a3[rs] = fmaf(sc3, tc, a3[rs]);
                    a2[rs] = fmaf(sc2, tc, a2[rs]);
                    a1[rs] = fmaf(sc1, tc, a1[rs]);
                    a0q[rs] = fmaf(sc0, tc, a0q[rs]);
                }
            }
        }
    }

    // ---- finish: per-thread fixed signs (n bits 1,2 <-> qubits 6,5), quad reduce
    float s6 = 1.f - 2.f * (float)(m & 1);
    float s5 = 1.f - 2.f * (float)(m >> 1);
#pragma unroll
    for (int rs = 0; rs < 4; rs++) {
        float o[8];
        o[0] = a0q[rs]; o[1] = a1[rs]; o[2] = a2[rs]; o[3] = a3[rs];
        o[4] = o4a[rs]; o[5] = s5 * tot[rs]; o[6] = s6 * tot[rs]; o[7] = o7[rs];
#pragma unroll
        for (int k = 0; k < 8; k++) {
            o[k] += __shfl_xor_sync(0xffffffffu, o[k], 1);
            o[k] += __shfl_xor_sync(0xffffffffu, o[k], 2);
        }
        if (m == 0) {
            int row = tile * 128 + w * 32 + (rs >> 1) * 16 + (rs & 1) * 8 + (l >> 2);
            float4* op = (float4*)(out + (size_t)row * 8);
            op[0] = make_float4(o[0], o[1], o[2], o[3]);
            op[1] = make_float4(o[4], o[5], o[6], o[7]);
        }
    }
}

// ---------------------------------------------------------------- launch
extern "C" void kernel_launch(void* const* d_in, const int* in_sizes, int n_in,
                              void* d_out, int out_size) {
    const float* x = (const float*)d_in[0];
    const float* w = (const float*)d_in[1];
    float* out = (float*)d_out;
    void* done_addr = nullptr;
    cudaGetSymbolAddress(&done_addr, g_done);
    cudaMemsetAsync(done_addr, 0, sizeof(int));
    cudaFuncSetAttribute(qsim_kernel, cudaFuncAttributeMaxDynamicSharedMemorySize, 98304);
    qsim_kernel<<<512, 128, 98304>>>(x, w, out);
}

// round 16
// speedup vs baseline: 1.2345x; 1.0293x over previous
#include <cuda_runtime.h>
#include <cuda_fp16.h>
#include <cstdint>

#define NQ 8
#define NL 4

// U fp16, K-major: rows 0..255 Re, 256..511 Im; 256 K-cols each. Row stride 512B.
__device__ __align__(16) __half g_U[512 * 256];

// ---------------------------------------------------------------- K1: build U
__global__ void build_u_kernel(const float* __restrict__ w) {
    int gw = (blockIdx.x * blockDim.x + threadIdx.x) >> 5;
    int lane = threadIdx.x & 31;
    if (gw >= 256) return;
    int j = gw;
    float re[8], im[8];
#pragma unroll
    for (int i = 0; i < 8; i++) { re[i] = 0.f; im[i] = 0.f; }
    if (lane == (j >> 3)) re[j & 7] = 1.0f;

    for (int l = 0; l < NL; l++) {
#pragma unroll
        for (int q = 0; q < NQ; q++) {
            float th = w[(l * NQ + q) * 2 + 0];
            float tz = w[(l * NQ + q) * 2 + 1];
            float c, s, pr, pi2;
            __sincosf(0.5f * th, &s, &c);
            __sincosf(0.5f * tz, &pi2, &pr);
            int bp = 7 - q;
            if (bp >= 3) {
                int lb = bp - 3;
                int myb = (lane >> lb) & 1;
                float oc = myb ? s : -s;
                float ph = myb ? pi2 : -pi2;
#pragma unroll
                for (int i = 0; i < 8; i++) {
                    float ore = __shfl_xor_sync(0xffffffffu, re[i], 1 << lb);
                    float oim = __shfl_xor_sync(0xffffffffu, im[i], 1 << lb);
                    float ur = c * re[i] + oc * ore;
                    float ui = c * im[i] + oc * oim;
                    re[i] = pr * ur - ph * ui;
                    im[i] = pr * ui + ph * ur;
                }
            } else {
                int mm = 1 << bp;
#pragma unroll
                for (int i = 0; i < 8; i++) {
                    if (i & mm) continue;
                    int i1 = i | mm;
                    float ur0 = c * re[i] - s * re[i1], ui0 = c * im[i] - s * im[i1];
                    float ur1 = s * re[i] + c * re[i1], ui1 = s * im[i] + c * im[i1];
                    re[i]  = pr * ur0 + pi2 * ui0;  im[i]  = pr * ui0 - pi2 * ur0;
                    re[i1] = pr * ur1 - pi2 * ui1;  im[i1] = pr * ui1 + pi2 * ur1;
                }
            }
        }
#pragma unroll
        for (int cc = 0; cc < 7; cc++) {
            int cb = 7 - cc, tb = 6 - cc;
            if (tb >= 3) {
                int tm = 1 << (tb - 3);
                int ctrl = (lane >> (cb - 3)) & 1;
#pragma unroll
                for (int i = 0; i < 8; i++) {
                    float ore = __shfl_xor_sync(0xffffffffu, re[i], tm);
                    float oim = __shfl_xor_sync(0xffffffffu, im[i], tm);
                    if (ctrl) { re[i] = ore; im[i] = oim; }
                }
            } else if (cb == 3) {
                if (lane & 1) {
#pragma unroll
                    for (int i = 0; i < 4; i++) {
                        float tr = re[i]; re[i] = re[i + 4]; re[i + 4] = tr;
                        float ti = im[i]; im[i] = im[i + 4]; im[i + 4] = ti;
                    }
                }
            } else {
                int tmsk = 1 << tb;
#pragma unroll
                for (int i = 0; i < 8; i++) {
                    if (((i >> cb) & 1) && !((i >> tb) & 1)) {
                        int i1 = i | tmsk;
                        float tr = re[i]; re[i] = re[i1]; re[i1] = tr;
                        float ti = im[i]; im[i] = im[i1]; im[i1] = ti;
                    }
                }
            }
        }
    }
#pragma unroll
    for (int i = 0; i < 8; i++) {
        int k = lane * 8 + i;
        g_U[k * 256 + j] = __float2half(re[i]);
        g_U[(k + 256) * 256 + j] = __float2half(im[i]);
    }
}

// ---------------------------------------------------------------- helpers
__device__ __forceinline__ uint32_t s2u(const void* p) {
    uint32_t r;
    asm("{ .reg .u64 t; cvta.to.shared.u64 t, %1; cvt.u32.u64 %0, t; }" : "=r"(r) : "l"(p));
    return r;
}

// NON-volatile: lets ptxas schedule/hoist LDSMs for software pipelining.
__device__ __forceinline__ void ldsm4(uint32_t& r0, uint32_t& r1, uint32_t& r2, uint32_t& r3,
                                      uint32_t addr) {
    asm("ldmatrix.sync.aligned.m8n8.x4.shared.b16 {%0,%1,%2,%3}, [%4];"
        : "=r"(r0), "=r"(r1), "=r"(r2), "=r"(r3) : "r"(addr));
}

// NON-volatile: pure compute, outputs consumed.
__device__ __forceinline__ void mma16816(float* c, const uint32_t* a, uint32_t b0, uint32_t b1) {
    asm("mma.sync.aligned.m16n8k16.row.col.f32.f16.f16.f32 "
        "{%0,%1,%2,%3}, {%4,%5,%6,%7}, {%8,%9}, {%0,%1,%2,%3};"
        : "+f"(c[0]), "+f"(c[1]), "+f"(c[2]), "+f"(c[3])
        : "r"(a[0]), "r"(a[1]), "r"(a[2]), "r"(a[3]), "r"(b0), "r"(b1));
}

// B chunk prefetch: 64 rows (32 Re + 32 Im) x 512B, XOR-swizzled, via cp.async.
// 128 threads -> 16 x 16B each.
#define PREFETCH(cc, bufi)                                                          \
    {                                                                               \
        _Pragma("unroll") for (int i_ = 0; i_ < 16; i_++) {                         \
            int idx_ = t + i_ * 128;                                                \
            int row_ = idx_ >> 5, kg_ = idx_ & 31;                                  \
            int g_ = 32 * (cc) + (row_ & 31) + ((row_ & 32) << 3);                  \
            const __half* src_ = g_U + g_ * 256 + kg_ * 8;                          \
            uint32_t dst_ = sb + (bufi) * 32768 + row_ * 512 +                      \
                            ((kg_ * 16) ^ ((row_ & 7) << 4));                       \
            asm volatile("cp.async.cg.shared.global [%0], [%1], 16;"                \
                         :: "r"(dst_), "l"(src_));                                  \
        }                                                                           \
        asm volatile("cp.async.commit_group;" ::: "memory");                        \
    }

// ---------------------------------------------------------------- K2
// M=32 rows/warp, 4 warps/CTA, grid 512. 8 chunks of 32 N-rows, 3-stage (96KB).
// Chunk loop kept rolled (#pragma unroll 1) so non-volatile LDSM can't CSE
// across chunks that reuse a buffer slot.
__global__ void __launch_bounds__(128, 2) qsim_kernel(const float* __restrict__ x,
                                                      float* __restrict__ out) {
    extern __shared__ char smem[];
    uint32_t sb = s2u(smem);
    int t = threadIdx.x, w = t >> 5, l = t & 31, m = l & 3;
    int tile = blockIdx.x;

    PREFETCH(0, 0);
    PREFETCH(1, 1);

    // ---- A fragments: 4 rows/thread (rg in {0,1} x rr in {0,1})
    uint32_t A[2][16][4];
#pragma unroll
    for (int rg = 0; rg < 2; rg++) {
#pragma unroll
        for (int rr = 0; rr < 2; rr++) {
            int row = tile * 128 + w * 32 + rg * 16 + rr * 8 + (l >> 2);
            const float4* xr4 = (const float4*)(x + (size_t)row * 8);
            float4 x0 = xr4[0], x1 = xr4[1];
            float xq[8] = {x0.x, x0.y, x0.z, x0.w, x1.x, x1.y, x1.z, x1.w};
            float c[8], s[8];
#pragma unroll
            for (int q = 0; q < 8; q++) __sincosf(0.5f * xq[q], &s[q], &c[q]);
            float hh[16];
            hh[0] = 1.f;
            int n = 1;
#pragma unroll
            for (int q = 0; q < 4; q++) {
#pragma unroll
                for (int mm = 15; mm >= 0; mm--) if (mm < n) {
                    float v = hh[mm];
                    hh[2 * mm] = v * c[q];
                    hh[2 * mm + 1] = v * s[q];
                }
                n *= 2;
            }
            float pa = ((m >> 1) ? s[5] : c[5]) * ((m & 1) ? s[6] : c[6]);
            float loA = c[4] * pa * c[7], loB = c[4] * pa * s[7];
            float loC = s[4] * pa * c[7], loD = s[4] * pa * s[7];
#pragma unroll
            for (int ss = 0; ss < 16; ss++) {
                float h = hh[ss];
                __half2 plo = __floats2half2_rn(h * loA, h * loB);
                __half2 phi = __floats2half2_rn(h * loC, h * loD);
                A[rg][ss][rr] = *(uint32_t*)&plo;
                A[rg][ss][2 + rr] = *(uint32_t*)&phi;
            }
        }
    }

    // ---- ldmatrix per-lane addressing
    int mR = l >> 3;
    int Rre = ((mR >> 1) << 3) + (l & 7);
    uint32_t offRe = Rre * 512;
    uint32_t koff = (mR & 1) << 4;
    uint32_t xr = (Rre & 7) << 4;

    // ---- accumulators per rowset rs = rg*2+rr
    float o7[4] = {0, 0, 0, 0}, o4a[4] = {0, 0, 0, 0}, tot[4] = {0, 0, 0, 0};
    float a3[4] = {0, 0, 0, 0}, a2[4] = {0, 0, 0, 0};
    float a1[4] = {0, 0, 0, 0}, a0q[4] = {0, 0, 0, 0};

    int cb = 0, pb = 2;
#pragma unroll 1
    for (int c = 0; c < 8; c++) {
        if (c < 7) asm volatile("cp.async.wait_group 1;" ::: "memory");
        else       asm volatile("cp.async.wait_group 0;" ::: "memory");
        __syncthreads();
        if (c + 2 < 8) {
            PREFETCH(c + 2, pb);
            pb = (pb == 2) ? 0 : pb + 1;
        }
        uint32_t bb = sb + cb * 32768;
        cb = (cb == 2) ? 0 : cb + 1;

#pragma unroll
        for (int ng = 0; ng < 2; ng++) {
            uint32_t bRe = bb + ng * 8192 + offRe;
            uint32_t bIm = bRe + 16384;

            float cR0[2][4] = {}, cR1[2][4] = {}, cI0[2][4] = {}, cI1[2][4] = {};
#pragma unroll
            for (int ss = 0; ss < 16; ss++) {
                uint32_t kb = (((uint32_t)(ss * 32)) | koff) ^ xr;
                uint32_t br0, br1, br2, br3, bi0, bi1, bi2, bi3;
                ldsm4(br0, br1, br2, br3, bRe + kb);
                ldsm4(bi0, bi1, bi2, bi3, bIm + kb);
#pragma unroll
                for (int rg = 0; rg < 2; rg++) {
                    mma16816(cR0[rg], A[rg][ss], br0, br1);
                    mma16816(cR1[rg], A[rg][ss], br2, br3);
                    mma16816(cI0[rg], A[rg][ss], bi0, bi1);
                    mma16816(cI1[rg], A[rg][ss], bi2, bi3);
                }
            }
            int cN = c * 2 + ng;
            float sc3 = 1.f - 2.f * (float)(cN & 1);
            float sc2 = 1.f - 2.f * (float)((cN >> 1) & 1);
            float sc1 = 1.f - 2.f * (float)((cN >> 2) & 1);
            float sc0 = 1.f - 2.f * (float)((cN >> 3) & 1);
#pragma unroll
            for (int rg = 0; rg < 2; rg++) {
#pragma unroll
                for (int rr = 0; rr < 2; rr++) {
                    int rs = rg * 2 + rr;
                    int i0 = rr * 2, i1 = rr * 2 + 1;
                    float p00 = fmaf(cR0[rg][i0], cR0[rg][i0], cI0[rg][i0] * cI0[rg][i0]);
                    float p01 = fmaf(cR0[rg][i1], cR0[rg][i1], cI0[rg][i1] * cI0[rg][i1]);
                    float p10 = fmaf(cR1[rg][i0], cR1[rg][i0], cI1[rg][i0] * cI1[rg][i0]);
                    float p11 = fmaf(cR1[rg][i1], cR1[rg][i1], cI1[rg][i1] * cI1[rg][i1]);
                    float s0 = p00 + p01, d0 = p00 - p01;
                    float s1 = p10 + p11, d1 = p10 - p11;
                    o7[rs] += d0 + d1;
                    o4a[rs] += s0 - s1;
                    float tc = s0 + s1;
                    tot[rs] += tc;
                    a3[rs] = fmaf(sc3, tc, a3[rs]);
                    a2[rs] = fmaf(sc2, tc, a2[rs]);
                    a1[rs] = fmaf(sc1, tc, a1[rs]);
                    a0q[rs] = fmaf(sc0, tc, a0q[rs]);
                }
            }
        }
    }

    // ---- finish: per-thread fixed signs (n bits 1,2 <-> qubits 6,5), quad reduce
    float s6 = 1.f - 2.f * (float)(m & 1);
    float s5 = 1.f - 2.f * (float)(m >> 1);
#pragma unroll
    for (int rs = 0; rs < 4; rs++) {
        float o[8];
        o[0] = a0q[rs]; o[1] = a1[rs]; o[2] = a2[rs]; o[3] = a3[rs];
        o[4] = o4a[rs]; o[5] = s5 * tot[rs]; o[6] = s6 * tot[rs]; o[7] = o7[rs];
#pragma unroll
        for (int k = 0; k < 8; k++) {
            o[k] += __shfl_xor_sync(0xffffffffu, o[k], 1);
            o[k] += __shfl_xor_sync(0xffffffffu, o[k], 2);
        }
        if (m == 0) {
            int row = tile * 128 + w * 32 + (rs >> 1) * 16 + (rs & 1) * 8 + (l >> 2);
            float4* op = (float4*)(out + (size_t)row * 8);
            op[0] = make_float4(o[0], o[1], o[2], o[3]);
            op[1] = make_float4(o[4], o[5], o[6], o[7]);
        }
    }
}

// ---------------------------------------------------------------- launch
extern "C" void kernel_launch(void* const* d_in, const int* in_sizes, int n_in,
                              void* d_out, int out_size) {
    const float* x = (const float*)d_in[0];
    const float* w = (const float*)d_in[1];
    float* out = (float*)d_out;
    cudaFuncSetAttribute(qsim_kernel, cudaFuncAttributeMaxDynamicSharedMemorySize, 98304);
    build_u_kernel<<<64, 128>>>(w);
    qsim_kernel<<<512, 128, 98304>>>(x, out);
}